// round 15
// baseline (speedup 1.0000x reference)
#include <cuda_runtime.h>

// CRF decoder loss: out[b] = score(b) - logZ(b)
// B=256, T=512, N=128 (N hardcoded = blockDim).
//
// Forward recursion done in exp-domain: alpha'_j = log( sum_i exp(a_i - m) * expT[i][j] ) + m + emit
// expT column j held entirely in registers per thread (static across all steps).

#define NSTATE 128

__global__ void __launch_bounds__(NSTATE, 1) crf_kernel(
    const float* __restrict__ lp,      // [B,T,N]
    const float* __restrict__ trans,   // [N,N]
    const float* __restrict__ startT,  // [N]
    const float* __restrict__ endT,    // [N]
    const int*   __restrict__ target,  // [B,T]
    const int*   __restrict__ lengths, // [B]
    float*       __restrict__ out,     // [B]
    int B, int T)
{
    const int j  = threadIdx.x;
    const int b0 = blockIdx.x * 2;
    if (b0 >= B) return;
    const int b1 = (b0 + 1 < B) ? (b0 + 1) : b0;

    __shared__ __align__(16) float2 sEA[NSTATE];  // exp(alpha - m) for both batches, indexed by i
    __shared__ float2 sW[4];                      // per-warp reduction scratch

    // ---- static: exp(transition) column j in registers ----
    float Tcol[NSTATE];
#pragma unroll
    for (int i = 0; i < NSTATE; ++i)
        Tcol[i] = __expf(trans[i * NSTATE + j]);

    const int len0 = lengths[b0];
    const int len1 = lengths[b1];
    const int tmax = (len0 > len1) ? len0 : len1;

    const float st = startT[j];
    const float* lp0 = lp + (size_t)b0 * T * NSTATE;
    const float* lp1 = lp + (size_t)b1 * T * NSTATE;

    float a0 = st + lp0[j];   // alpha at t=0
    float a1 = st + lp1[j];

    // prefetch emission for t=1
    float e0 = 0.f, e1 = 0.f;
    if (tmax > 1) {
        e0 = lp0[NSTATE + j];
        e1 = lp1[NSTATE + j];
    }

    // ---- forward recursion ----
    for (int t = 1; t < tmax; ++t) {
        // prefetch next step's emissions (hide DRAM latency behind this step)
        float en0 = 0.f, en1 = 0.f;
        if (t + 1 < tmax) {
            en0 = lp0[(size_t)(t + 1) * NSTATE + j];
            en1 = lp1[(size_t)(t + 1) * NSTATE + j];
        }

        // block max of alpha (both batches, interleaved shfl chains)
        float m0 = a0, m1 = a1;
#pragma unroll
        for (int o = 16; o > 0; o >>= 1) {
            m0 = fmaxf(m0, __shfl_xor_sync(0xffffffffu, m0, o));
            m1 = fmaxf(m1, __shfl_xor_sync(0xffffffffu, m1, o));
        }
        if ((j & 31) == 0) sW[j >> 5] = make_float2(m0, m1);
        __syncthreads();
        {
            float2 w0 = sW[0], w1 = sW[1], w2 = sW[2], w3 = sW[3];
            m0 = fmaxf(fmaxf(w0.x, w1.x), fmaxf(w2.x, w3.x));
            m1 = fmaxf(fmaxf(w0.y, w1.y), fmaxf(w2.y, w3.y));
        }

        sEA[j] = make_float2(__expf(a0 - m0), __expf(a1 - m1));
        __syncthreads();

        // dot: s_j = sum_i expA[i] * expT[i][j], expT from registers,
        // expA via broadcast LDS.128 (2 i's x 2 batches per load)
        float s0a = 0.f, s0b = 0.f, s1a = 0.f, s1b = 0.f;
#pragma unroll
        for (int i = 0; i < NSTATE; i += 2) {
            float4 e = *reinterpret_cast<const float4*>(&sEA[i]);
            s0a = fmaf(e.x, Tcol[i],     s0a);
            s1a = fmaf(e.y, Tcol[i],     s1a);
            s0b = fmaf(e.z, Tcol[i + 1], s0b);
            s1b = fmaf(e.w, Tcol[i + 1], s1b);
        }
        float n0 = __logf(s0a + s0b) + m0 + e0;
        float n1 = __logf(s1a + s1b) + m1 + e1;
        a0 = (t < len0) ? n0 : a0;
        a1 = (t < len1) ? n1 : a1;
        e0 = en0; e1 = en1;
    }

    // ---- logZ = logsumexp_j(alpha_j + end_j) ----
    __syncthreads();   // protect sW reuse against last loop iteration
    const float ed = endT[j];
    float v0 = a0 + ed;
    float v1 = a1 + ed;

    float m0 = v0, m1 = v1;
#pragma unroll
    for (int o = 16; o > 0; o >>= 1) {
        m0 = fmaxf(m0, __shfl_xor_sync(0xffffffffu, m0, o));
        m1 = fmaxf(m1, __shfl_xor_sync(0xffffffffu, m1, o));
    }
    if ((j & 31) == 0) sW[j >> 5] = make_float2(m0, m1);
    __syncthreads();
    {
        float2 w0 = sW[0], w1 = sW[1], w2 = sW[2], w3 = sW[3];
        m0 = fmaxf(fmaxf(w0.x, w1.x), fmaxf(w2.x, w3.x));
        m1 = fmaxf(fmaxf(w0.y, w1.y), fmaxf(w2.y, w3.y));
    }
    float p0 = __expf(v0 - m0);
    float p1 = __expf(v1 - m1);
#pragma unroll
    for (int o = 16; o > 0; o >>= 1) {
        p0 += __shfl_xor_sync(0xffffffffu, p0, o);
        p1 += __shfl_xor_sync(0xffffffffu, p1, o);
    }
    __syncthreads();   // all reads of sW (max phase) done before overwrite
    if ((j & 31) == 0) sW[j >> 5] = make_float2(p0, p1);
    __syncthreads();
    float logZ0, logZ1;
    {
        float2 w0 = sW[0], w1 = sW[1], w2 = sW[2], w3 = sW[3];
        logZ0 = __logf(w0.x + w1.x + w2.x + w3.x) + m0;
        logZ1 = __logf(w0.y + w1.y + w2.y + w3.y) + m1;
    }

    // ---- score(b) = sum emissions + transitions + start + end ----
    const int* tg0 = target + (size_t)b0 * T;
    const int* tg1 = target + (size_t)b1 * T;
    float sc0 = 0.f, sc1 = 0.f;
    for (int t = j; t < T; t += NSTATE) {
        int g0 = tg0[t];
        if (t < len0) {
            sc0 += lp0[(size_t)t * NSTATE + g0];
            if (t >= 1) sc0 += trans[tg0[t - 1] * NSTATE + g0];
        }
        int g1 = tg1[t];
        if (t < len1) {
            sc1 += lp1[(size_t)t * NSTATE + g1];
            if (t >= 1) sc1 += trans[tg1[t - 1] * NSTATE + g1];
        }
    }
    if (j == 0) {
        sc0 += startT[tg0[0]] + endT[tg0[len0 - 1]];
        sc1 += startT[tg1[0]] + endT[tg1[len1 - 1]];
    }
#pragma unroll
    for (int o = 16; o > 0; o >>= 1) {
        sc0 += __shfl_xor_sync(0xffffffffu, sc0, o);
        sc1 += __shfl_xor_sync(0xffffffffu, sc1, o);
    }
    __syncthreads();   // protect sW reuse
    if ((j & 31) == 0) sW[j >> 5] = make_float2(sc0, sc1);
    __syncthreads();
    if (j == 0) {
        float2 w0 = sW[0], w1 = sW[1], w2 = sW[2], w3 = sW[3];
        float S0 = w0.x + w1.x + w2.x + w3.x;
        float S1 = w0.y + w1.y + w2.y + w3.y;
        out[b0] = S0 - logZ0;
        if (b1 != b0) out[b1] = S1 - logZ1;
    }
}

extern "C" void kernel_launch(void* const* d_in, const int* in_sizes, int n_in,
                              void* d_out, int out_size) {
    const float* lp      = (const float*)d_in[0];
    const float* trans   = (const float*)d_in[1];
    const float* startT  = (const float*)d_in[2];
    const float* endT    = (const float*)d_in[3];
    const int*   target  = (const int*)d_in[4];
    const int*   lengths = (const int*)d_in[5];
    float*       out     = (float*)d_out;

    const int B = in_sizes[5];
    const int T = in_sizes[4] / B;

    const int grid = (B + 1) / 2;
    crf_kernel<<<grid, NSTATE>>>(lp, trans, startT, endT, target, lengths, out, B, T);
}

// round 16
// speedup vs baseline: 1.0039x; 1.0039x over previous
#include <cuda_runtime.h>

// CRF decoder loss: out[b] = score(b) - logZ(b)
// B=256, T=512, N=128 (N hardcoded = blockDim).
//
// Forward recursion done in exp-domain: alpha'_j = log( sum_i exp(a_i - m) * expT[i][j] ) + m + emit
// expT column j held entirely in registers per thread (static across all steps).

#define NSTATE 128

__global__ void __launch_bounds__(NSTATE, 1) crf_kernel(
    const float* __restrict__ lp,      // [B,T,N]
    const float* __restrict__ trans,   // [N,N]
    const float* __restrict__ startT,  // [N]
    const float* __restrict__ endT,    // [N]
    const int*   __restrict__ target,  // [B,T]
    const int*   __restrict__ lengths, // [B]
    float*       __restrict__ out,     // [B]
    int B, int T)
{
    const int j  = threadIdx.x;
    const int b0 = blockIdx.x * 2;
    if (b0 >= B) return;
    const int b1 = (b0 + 1 < B) ? (b0 + 1) : b0;

    __shared__ __align__(16) float2 sEA[NSTATE];  // exp(alpha - m) for both batches, indexed by i
    __shared__ float2 sW[4];                      // per-warp reduction scratch

    // ---- static: exp(transition) column j in registers ----
    float Tcol[NSTATE];
#pragma unroll
    for (int i = 0; i < NSTATE; ++i)
        Tcol[i] = __expf(trans[i * NSTATE + j]);

    const int len0 = lengths[b0];
    const int len1 = lengths[b1];
    const int tmax = (len0 > len1) ? len0 : len1;

    const float st = startT[j];
    const float* lp0 = lp + (size_t)b0 * T * NSTATE;
    const float* lp1 = lp + (size_t)b1 * T * NSTATE;

    float a0 = st + lp0[j];   // alpha at t=0
    float a1 = st + lp1[j];

    // prefetch emission for t=1
    float e0 = 0.f, e1 = 0.f;
    if (tmax > 1) {
        e0 = lp0[NSTATE + j];
        e1 = lp1[NSTATE + j];
    }

    // ---- forward recursion ----
    for (int t = 1; t < tmax; ++t) {
        // prefetch next step's emissions (hide DRAM latency behind this step)
        float en0 = 0.f, en1 = 0.f;
        if (t + 1 < tmax) {
            en0 = lp0[(size_t)(t + 1) * NSTATE + j];
            en1 = lp1[(size_t)(t + 1) * NSTATE + j];
        }

        // block max of alpha (both batches, interleaved shfl chains)
        float m0 = a0, m1 = a1;
#pragma unroll
        for (int o = 16; o > 0; o >>= 1) {
            m0 = fmaxf(m0, __shfl_xor_sync(0xffffffffu, m0, o));
            m1 = fmaxf(m1, __shfl_xor_sync(0xffffffffu, m1, o));
        }
        if ((j & 31) == 0) sW[j >> 5] = make_float2(m0, m1);
        __syncthreads();
        {
            float2 w0 = sW[0], w1 = sW[1], w2 = sW[2], w3 = sW[3];
            m0 = fmaxf(fmaxf(w0.x, w1.x), fmaxf(w2.x, w3.x));
            m1 = fmaxf(fmaxf(w0.y, w1.y), fmaxf(w2.y, w3.y));
        }

        sEA[j] = make_float2(__expf(a0 - m0), __expf(a1 - m1));
        __syncthreads();

        // dot: s_j = sum_i expA[i] * expT[i][j], expT from registers,
        // expA via broadcast LDS.128 (2 i's x 2 batches per load)
        float s0a = 0.f, s0b = 0.f, s1a = 0.f, s1b = 0.f;
#pragma unroll
        for (int i = 0; i < NSTATE; i += 2) {
            float4 e = *reinterpret_cast<const float4*>(&sEA[i]);
            s0a = fmaf(e.x, Tcol[i],     s0a);
            s1a = fmaf(e.y, Tcol[i],     s1a);
            s0b = fmaf(e.z, Tcol[i + 1], s0b);
            s1b = fmaf(e.w, Tcol[i + 1], s1b);
        }
        float n0 = __logf(s0a + s0b) + m0 + e0;
        float n1 = __logf(s1a + s1b) + m1 + e1;
        a0 = (t < len0) ? n0 : a0;
        a1 = (t < len1) ? n1 : a1;
        e0 = en0; e1 = en1;
    }

    // ---- logZ = logsumexp_j(alpha_j + end_j) ----
    __syncthreads();   // protect sW reuse against last loop iteration
    const float ed = endT[j];
    float v0 = a0 + ed;
    float v1 = a1 + ed;

    float m0 = v0, m1 = v1;
#pragma unroll
    for (int o = 16; o > 0; o >>= 1) {
        m0 = fmaxf(m0, __shfl_xor_sync(0xffffffffu, m0, o));
        m1 = fmaxf(m1, __shfl_xor_sync(0xffffffffu, m1, o));
    }
    if ((j & 31) == 0) sW[j >> 5] = make_float2(m0, m1);
    __syncthreads();
    {
        float2 w0 = sW[0], w1 = sW[1], w2 = sW[2], w3 = sW[3];
        m0 = fmaxf(fmaxf(w0.x, w1.x), fmaxf(w2.x, w3.x));
        m1 = fmaxf(fmaxf(w0.y, w1.y), fmaxf(w2.y, w3.y));
    }
    float p0 = __expf(v0 - m0);
    float p1 = __expf(v1 - m1);
#pragma unroll
    for (int o = 16; o > 0; o >>= 1) {
        p0 += __shfl_xor_sync(0xffffffffu, p0, o);
        p1 += __shfl_xor_sync(0xffffffffu, p1, o);
    }
    __syncthreads();   // all reads of sW (max phase) done before overwrite
    if ((j & 31) == 0) sW[j >> 5] = make_float2(p0, p1);
    __syncthreads();
    float logZ0, logZ1;
    {
        float2 w0 = sW[0], w1 = sW[1], w2 = sW[2], w3 = sW[3];
        logZ0 = __logf(w0.x + w1.x + w2.x + w3.x) + m0;
        logZ1 = __logf(w0.y + w1.y + w2.y + w3.y) + m1;
    }

    // ---- score(b) = sum emissions + transitions + start + end ----
    const int* tg0 = target + (size_t)b0 * T;
    const int* tg1 = target + (size_t)b1 * T;
    float sc0 = 0.f, sc1 = 0.f;
    for (int t = j; t < T; t += NSTATE) {
        int g0 = tg0[t];
        if (t < len0) {
            sc0 += lp0[(size_t)t * NSTATE + g0];
            if (t >= 1) sc0 += trans[tg0[t - 1] * NSTATE + g0];
        }
        int g1 = tg1[t];
        if (t < len1) {
            sc1 += lp1[(size_t)t * NSTATE + g1];
            if (t >= 1) sc1 += trans[tg1[t - 1] * NSTATE + g1];
        }
    }
    if (j == 0) {
        sc0 += startT[tg0[0]] + endT[tg0[len0 - 1]];
        sc1 += startT[tg1[0]] + endT[tg1[len1 - 1]];
    }
#pragma unroll
    for (int o = 16; o > 0; o >>= 1) {
        sc0 += __shfl_xor_sync(0xffffffffu, sc0, o);
        sc1 += __shfl_xor_sync(0xffffffffu, sc1, o);
    }
    __syncthreads();   // protect sW reuse
    if ((j & 31) == 0) sW[j >> 5] = make_float2(sc0, sc1);
    __syncthreads();
    if (j == 0) {
        float2 w0 = sW[0], w1 = sW[1], w2 = sW[2], w3 = sW[3];
        float S0 = w0.x + w1.x + w2.x + w3.x;
        float S1 = w0.y + w1.y + w2.y + w3.y;
        out[b0] = S0 - logZ0;
        if (b1 != b0) out[b1] = S1 - logZ1;
    }
}

extern "C" void kernel_launch(void* const* d_in, const int* in_sizes, int n_in,
                              void* d_out, int out_size) {
    const float* lp      = (const float*)d_in[0];
    const float* trans   = (const float*)d_in[1];
    const float* startT  = (const float*)d_in[2];
    const float* endT    = (const float*)d_in[3];
    const int*   target  = (const int*)d_in[4];
    const int*   lengths = (const int*)d_in[5];
    float*       out     = (float*)d_out;

    const int B = in_sizes[5];
    const int T = in_sizes[4] / B;

    const int grid = (B + 1) / 2;
    crf_kernel<<<grid, NSTATE>>>(lp, trans, startT, endT, target, lengths, out, B, T);
}